// round 15
// baseline (speedup 1.0000x reference)
#include <cuda_runtime.h>
#include <cuda_fp16.h>

// Problem constants
#define NB   32      // batch
#define NIN  2048    // input capsules
#define ROW  1024    // NOUT*DD floats per (b,i) row
// Pass 0 (column-per-thread, high occupancy):
#define SLICES0 32   // blocks per batch item (grid 1024, ~6 blocks/SM)
#define RPB0 (NIN / SLICES0)   // 64 rows per block
// Weighted passes (row-per-warp over fp16 shadow):
#define SLICES 8     // blocks per batch item (grid 256 = single resident wave)
#define WPBLK  8
#define IPW  32      // rows per warp

// Scratch (static device memory; no runtime allocation)
__device__ float  g_partials[NB * SLICES0 * ROW];   // 4 MB
__device__ float  g_ow[NB * ROW];                   // out0 / out0+out1
__device__ float2 g_xh[(size_t)NB * NIN * 256];     // fp16 shadow, 128 MB
__device__ int    g_cnt[NB];                        // zero-init; self-resetting

// ---------------------------------------------------------------------------
// Last-block epilogue: reduce NSL partials in fixed order, + bias, squash,
// update g_ow / write output, reset counter (replay-safe).
// ---------------------------------------------------------------------------
template<int NSL, int OW_MODE, int FINAL_OUT>
__device__ __forceinline__ void last_block_epilogue(
    int b, const float* __restrict__ bias, float* __restrict__ dout)
{
    const int t = threadIdx.x;
    const float4* pp = reinterpret_cast<const float4*>(g_partials) + (size_t)b * NSL * 256;
    float4 r = make_float4(0.f, 0.f, 0.f, 0.f);
#pragma unroll 8
    for (int s2 = 0; s2 < NSL; s2++) {
        float4 v = __ldcg(pp + s2 * 256 + t);
        r.x += v.x; r.y += v.y; r.z += v.z; r.w += v.w;
    }
    float4 bb = reinterpret_cast<const float4*>(bias)[t];
    r.x += bb.x; r.y += bb.y; r.z += bb.z; r.w += bb.w;

    float n2 = r.x * r.x + r.y * r.y + r.z * r.z + r.w * r.w;
    n2 += __shfl_xor_sync(0xffffffffu, n2, 1);
    n2 += __shfl_xor_sync(0xffffffffu, n2, 2);
    float scale = n2 / ((1.0f + n2) * sqrtf(n2 + 1e-7f));
    float4 o = make_float4(r.x * scale, r.y * scale, r.z * scale, r.w * scale);

    if (FINAL_OUT)
        reinterpret_cast<float4*>(dout)[b * 256 + t] = o;
    if (OW_MODE == 1) {
        reinterpret_cast<float4*>(g_ow)[b * 256 + t] = o;
    } else if (OW_MODE == 2) {
        float4 c = reinterpret_cast<const float4*>(g_ow)[b * 256 + t];
        c.x += o.x; c.y += o.y; c.z += o.z; c.w += o.w;
        reinterpret_cast<float4*>(g_ow)[b * 256 + t] = c;
    }
    if (t == 0) g_cnt[b] = 0;
}

// Publish-then-arrive (all threads stored + fenced BEFORE t0 increments).
template<int NSL>
__device__ __forceinline__ bool arrive_last(int b)
{
    __threadfence();
    __syncthreads();
    __shared__ int isLast;
    if (threadIdx.x == 0) {
        int old = atomicAdd(&g_cnt[b], 1);
        isLast = (old == NSL - 1);
    }
    __syncthreads();
    return isLast != 0;
}

// ---------------------------------------------------------------------------
// Pass 0: column-per-thread, ~48 warps/SM. Reads fp32, emits fp16 shadow,
// accumulates uniform (1/64) sum.  (unchanged from R13 — measured 71.5us)
// ---------------------------------------------------------------------------
__global__ void __launch_bounds__(256, 6)
route_pass0(const float* __restrict__ x, const float* __restrict__ bias,
            float* __restrict__ dout)
{
    const int b     = blockIdx.x >> 5;
    const int slice = blockIdx.x & 31;
    const int t     = threadIdx.x;

    const float4* base = reinterpret_cast<const float4*>(x)
        + ((size_t)b * NIN + (size_t)slice * RPB0) * 256;
    float2* hbase = g_xh + ((size_t)b * NIN + (size_t)slice * RPB0) * 256;

    float4 acc = make_float4(0.f, 0.f, 0.f, 0.f);
    for (int ii = 0; ii < RPB0; ii += 8) {
        float4 v[8];
#pragma unroll
        for (int k = 0; k < 8; k++) v[k] = __ldcs(base + (size_t)(ii + k) * 256 + t);
#pragma unroll
        for (int k = 0; k < 8; k++) {
            __half2 h0 = __floats2half2_rn(v[k].x, v[k].y);
            __half2 h1 = __floats2half2_rn(v[k].z, v[k].w);
            float2 st;
            st.x = __uint_as_float(*reinterpret_cast<unsigned*>(&h0));
            st.y = __uint_as_float(*reinterpret_cast<unsigned*>(&h1));
            hbase[(size_t)(ii + k) * 256 + t] = st;
            acc.x += v[k].x; acc.y += v[k].y; acc.z += v[k].z; acc.w += v[k].w;
        }
    }
    acc.x *= 0.015625f; acc.y *= 0.015625f;
    acc.z *= 0.015625f; acc.w *= 0.015625f;

    reinterpret_cast<float4*>(g_partials)[((size_t)b * SLICES0 + slice) * 256 + t] = acc;

    if (!arrive_last<SLICES0>(b)) return;
    last_block_epilogue<SLICES0, 1, 0>(b, bias, dout);
}

// Unpack helper: float4 of 8 halves -> 8 floats (e[0..7])
__device__ __forceinline__ void unpack8(const float4& hv, float* e)
{
    const __half2* hh = reinterpret_cast<const __half2*>(&hv);
    float2 a0 = __half22float2(hh[0]);
    float2 a1 = __half22float2(hh[1]);
    float2 a2 = __half22float2(hh[2]);
    float2 a3 = __half22float2(hh[3]);
    e[0] = a0.x; e[1] = a0.y; e[2] = a1.x; e[3] = a1.y;
    e[4] = a2.x; e[5] = a2.y; e[6] = a3.x; e[7] = a3.y;
}

// ---------------------------------------------------------------------------
// Weighted passes over the fp16 shadow: row-per-warp, x4-row unroll
// (16 LDG.128 in flight), processed as two interleaved row-pairs. Packed hv
// kept live; unpacked twice (dot, then accumulate) to bound registers.
// fp16 mapping: float4 g = lane + 32k (k=0..3) -> halves [8g, 8g+8)
//   -> capsule j = (lane>>1) + 16k. Dot over d=16: xor 1. Softmax: xor 2..16.
// ---------------------------------------------------------------------------
template<int OW_MODE, int FINAL_OUT, int REVERSE>
__global__ void __launch_bounds__(256, 2)
route_passH(const float* __restrict__ bias, float* __restrict__ dout)
{
    const int b     = blockIdx.x >> 3;
    const int slice = blockIdx.x & 7;
    const int wloc  = threadIdx.x >> 5;
    const int wb    = (slice << 3) | wloc;
    const int lane  = threadIdx.x & 31;

    __shared__ float4 wsh[256];            // 4 KB: ow vector for this b
    __shared__ float4 sbuf[WPBLK * 256];   // 32 KB: tail reduce

    {
        const float4* owp = reinterpret_cast<const float4*>(g_ow) + (size_t)b * 256;
        wsh[threadIdx.x] = owp[threadIdx.x];
    }
    __syncthreads();

    float4 acc[8];
#pragma unroll
    for (int k = 0; k < 8; k++) acc[k] = make_float4(0.f, 0.f, 0.f, 0.f);

    const float4* hbase = reinterpret_cast<const float4*>(g_xh)
        + ((size_t)b * NIN + (size_t)wb * IPW) * 128;   // 128 float4 per row

    for (int it = 0; it < IPW; it += 4) {
        const int ib = REVERSE ? (IPW - 4 - it) : it;

        // 16 LDG.128 issued up front (4 rows x 4 per thread)
        float4 hv[16];
#pragma unroll
        for (int r = 0; r < 4; r++)
#pragma unroll
            for (int k = 0; k < 4; k++)
                hv[r * 4 + k] = hbase[(size_t)(ib + r) * 128 + lane + 32 * k];

#pragma unroll
        for (int pr = 0; pr < 2; pr++) {
            const float4* h0 = &hv[(2 * pr) * 4];
            const float4* h1 = &hv[(2 * pr + 1) * 4];

            float p0[4], p1[4];
#pragma unroll
            for (int k = 0; k < 4; k++) {
                int g = lane + 32 * k;
                float4 wa = wsh[2 * g], wb2 = wsh[2 * g + 1];
                float e0[8], e1[8];
                unpack8(h0[k], e0);
                unpack8(h1[k], e1);
                float t0 = e0[0]*wa.x + e0[1]*wa.y + e0[2]*wa.z + e0[3]*wa.w
                         + e0[4]*wb2.x + e0[5]*wb2.y + e0[6]*wb2.z + e0[7]*wb2.w;
                float t1 = e1[0]*wa.x + e1[1]*wa.y + e1[2]*wa.z + e1[3]*wa.w
                         + e1[4]*wb2.x + e1[5]*wb2.y + e1[6]*wb2.z + e1[7]*wb2.w;
                t0 += __shfl_xor_sync(0xffffffffu, t0, 1);   // full dot over d=16
                t1 += __shfl_xor_sync(0xffffffffu, t1, 1);
                p0[k] = t0; p1[k] = t1;
            }
            // softmax over 64 j (two rows interleaved)
            float m0 = fmaxf(fmaxf(p0[0], p0[1]), fmaxf(p0[2], p0[3]));
            float m1 = fmaxf(fmaxf(p1[0], p1[1]), fmaxf(p1[2], p1[3]));
            m0 = fmaxf(m0, __shfl_xor_sync(0xffffffffu, m0, 2));
            m1 = fmaxf(m1, __shfl_xor_sync(0xffffffffu, m1, 2));
            m0 = fmaxf(m0, __shfl_xor_sync(0xffffffffu, m0, 4));
            m1 = fmaxf(m1, __shfl_xor_sync(0xffffffffu, m1, 4));
            m0 = fmaxf(m0, __shfl_xor_sync(0xffffffffu, m0, 8));
            m1 = fmaxf(m1, __shfl_xor_sync(0xffffffffu, m1, 8));
            m0 = fmaxf(m0, __shfl_xor_sync(0xffffffffu, m0, 16));
            m1 = fmaxf(m1, __shfl_xor_sync(0xffffffffu, m1, 16));
            float a0[4], a1[4], s0 = 0.f, s1 = 0.f;
#pragma unroll
            for (int k = 0; k < 4; k++) {
                a0[k] = __expf(p0[k] - m0); s0 += a0[k];
                a1[k] = __expf(p1[k] - m1); s1 += a1[k];
            }
            s0 += __shfl_xor_sync(0xffffffffu, s0, 2);
            s1 += __shfl_xor_sync(0xffffffffu, s1, 2);
            s0 += __shfl_xor_sync(0xffffffffu, s0, 4);
            s1 += __shfl_xor_sync(0xffffffffu, s1, 4);
            s0 += __shfl_xor_sync(0xffffffffu, s0, 8);
            s1 += __shfl_xor_sync(0xffffffffu, s1, 8);
            s0 += __shfl_xor_sync(0xffffffffu, s0, 16);
            s1 += __shfl_xor_sync(0xffffffffu, s1, 16);
            float inv0 = 1.0f / s0, inv1 = 1.0f / s1;

            // accumulate: re-unpack hv (cheap ALU) and fma into acc
#pragma unroll
            for (int k = 0; k < 4; k++) {
                float ak0 = a0[k] * inv0;
                float ak1 = a1[k] * inv1;
                float e0[8], e1[8];
                unpack8(h0[k], e0);
                unpack8(h1[k], e1);
                acc[2*k].x   = fmaf(ak1, e1[0], fmaf(ak0, e0[0], acc[2*k].x));
                acc[2*k].y   = fmaf(ak1, e1[1], fmaf(ak0, e0[1], acc[2*k].y));
                acc[2*k].z   = fmaf(ak1, e1[2], fmaf(ak0, e0[2], acc[2*k].z));
                acc[2*k].w   = fmaf(ak1, e1[3], fmaf(ak0, e0[3], acc[2*k].w));
                acc[2*k+1].x = fmaf(ak1, e1[4], fmaf(ak0, e0[4], acc[2*k+1].x));
                acc[2*k+1].y = fmaf(ak1, e1[5], fmaf(ak0, e0[5], acc[2*k+1].y));
                acc[2*k+1].z = fmaf(ak1, e1[6], fmaf(ak0, e0[6], acc[2*k+1].z));
                acc[2*k+1].w = fmaf(ak1, e1[7], fmaf(ak0, e0[7], acc[2*k+1].w));
            }
        }
    }

    // in-block reduce: write accs to canonical float4 positions
#pragma unroll
    for (int k = 0; k < 4; k++) {
        int g = lane + 32 * k;
        sbuf[wloc * 256 + 2 * g]     = acc[2 * k];
        sbuf[wloc * 256 + 2 * g + 1] = acc[2 * k + 1];
    }
    __syncthreads();

    const int t = threadIdx.x;
    float4 s = make_float4(0.f, 0.f, 0.f, 0.f);
#pragma unroll
    for (int w2 = 0; w2 < WPBLK; w2++) {
        float4 v = sbuf[w2 * 256 + t];
        s.x += v.x; s.y += v.y; s.z += v.z; s.w += v.w;
    }
    reinterpret_cast<float4*>(g_partials)[((size_t)b * SLICES + slice) * 256 + t] = s;

    if (!arrive_last<SLICES>(b)) return;
    last_block_epilogue<SLICES, OW_MODE, FINAL_OUT>(b, bias, dout);
}

extern "C" void kernel_launch(void* const* d_in, const int* in_sizes, int n_in,
                              void* d_out, int out_size)
{
    const float* x    = (const float*)d_in[0];   // [32, 2048, 64, 16]
    const float* bias = (const float*)d_in[1];   // [64, 16]
    float* out = (float*)d_out;                  // [32, 64, 16]

    (void)in_sizes; (void)n_in; (void)out_size;

    dim3 g0(NB * SLICES0), gW(NB * SLICES), blk(256);

    // Round 0 (forward, column-mapped): uniform 1/64 + fp16 shadow; g_ow = out0
    route_pass0<<<g0, blk>>>(x, bias, out);
    // Round 1 (REVERSE over shadow): softmax(dot(x, out0)); g_ow = out0+out1
    route_passH<2, 0, 1><<<gW, blk>>>(bias, out);
    // Round 2 (forward over shadow): softmax(dot(x, out0+out1)); write output
    route_passH<0, 1, 0><<<gW, blk>>>(bias, out);
}

// round 17
// speedup vs baseline: 1.1314x; 1.1314x over previous
#include <cuda_runtime.h>
#include <cuda_fp16.h>

// Problem constants
#define NB   32      // batch
#define NIN  2048    // input capsules
#define ROW  1024    // NOUT*DD floats per (b,i) row
// Pass 0 (column-per-thread, high occupancy):
#define SLICES0 32   // blocks per batch item (grid 1024, ~6 blocks/SM)
#define RPB0 (NIN / SLICES0)   // 64 rows per block
// Weighted passes (row-per-warp over fp16 shadow):
#define SLICES 8     // blocks per batch item (grid 256 = single resident wave)
#define WPBLK  8
#define IPW  32      // rows per warp

// Scratch (static device memory; no runtime allocation)
__device__ float  g_partials[NB * SLICES0 * ROW];   // 4 MB
__device__ float  g_ow[NB * ROW];                   // out0 / out0+out1
__device__ float2 g_xh[(size_t)NB * NIN * 256];     // fp16 shadow, 128 MB
__device__ int    g_cnt[NB];                        // zero-init; self-resetting

// ---------------------------------------------------------------------------
// Last-block epilogue: reduce NSL partials in fixed order, + bias, squash,
// update g_ow / write output, reset counter (replay-safe).
// ---------------------------------------------------------------------------
template<int NSL, int OW_MODE, int FINAL_OUT>
__device__ __forceinline__ void last_block_epilogue(
    int b, const float* __restrict__ bias, float* __restrict__ dout)
{
    const int t = threadIdx.x;
    const float4* pp = reinterpret_cast<const float4*>(g_partials) + (size_t)b * NSL * 256;
    float4 r = make_float4(0.f, 0.f, 0.f, 0.f);
#pragma unroll 8
    for (int s2 = 0; s2 < NSL; s2++) {
        float4 v = __ldcg(pp + s2 * 256 + t);
        r.x += v.x; r.y += v.y; r.z += v.z; r.w += v.w;
    }
    float4 bb = reinterpret_cast<const float4*>(bias)[t];
    r.x += bb.x; r.y += bb.y; r.z += bb.z; r.w += bb.w;

    float n2 = r.x * r.x + r.y * r.y + r.z * r.z + r.w * r.w;
    n2 += __shfl_xor_sync(0xffffffffu, n2, 1);
    n2 += __shfl_xor_sync(0xffffffffu, n2, 2);
    float scale = n2 / ((1.0f + n2) * sqrtf(n2 + 1e-7f));
    float4 o = make_float4(r.x * scale, r.y * scale, r.z * scale, r.w * scale);

    if (FINAL_OUT)
        reinterpret_cast<float4*>(dout)[b * 256 + t] = o;
    if (OW_MODE == 1) {
        reinterpret_cast<float4*>(g_ow)[b * 256 + t] = o;
    } else if (OW_MODE == 2) {
        float4 c = reinterpret_cast<const float4*>(g_ow)[b * 256 + t];
        c.x += o.x; c.y += o.y; c.z += o.z; c.w += o.w;
        reinterpret_cast<float4*>(g_ow)[b * 256 + t] = c;
    }
    if (t == 0) g_cnt[b] = 0;
}

// Publish-then-arrive (all threads stored + fenced BEFORE t0 increments).
template<int NSL>
__device__ __forceinline__ bool arrive_last(int b)
{
    __threadfence();
    __syncthreads();
    __shared__ int isLast;
    if (threadIdx.x == 0) {
        int old = atomicAdd(&g_cnt[b], 1);
        isLast = (old == NSL - 1);
    }
    __syncthreads();
    return isLast != 0;
}

// ---------------------------------------------------------------------------
// Pass 0: column-per-thread, ~48 warps/SM. Reads fp32, emits fp16 shadow,
// accumulates uniform (1/64) sum.  (unchanged from R13 — measured 71.5us)
// ---------------------------------------------------------------------------
__global__ void __launch_bounds__(256, 6)
route_pass0(const float* __restrict__ x, const float* __restrict__ bias,
            float* __restrict__ dout)
{
    const int b     = blockIdx.x >> 5;
    const int slice = blockIdx.x & 31;
    const int t     = threadIdx.x;

    const float4* base = reinterpret_cast<const float4*>(x)
        + ((size_t)b * NIN + (size_t)slice * RPB0) * 256;
    float2* hbase = g_xh + ((size_t)b * NIN + (size_t)slice * RPB0) * 256;

    float4 acc = make_float4(0.f, 0.f, 0.f, 0.f);
    for (int ii = 0; ii < RPB0; ii += 8) {
        float4 v[8];
#pragma unroll
        for (int k = 0; k < 8; k++) v[k] = __ldcs(base + (size_t)(ii + k) * 256 + t);
#pragma unroll
        for (int k = 0; k < 8; k++) {
            __half2 h0 = __floats2half2_rn(v[k].x, v[k].y);
            __half2 h1 = __floats2half2_rn(v[k].z, v[k].w);
            float2 st;
            st.x = __uint_as_float(*reinterpret_cast<unsigned*>(&h0));
            st.y = __uint_as_float(*reinterpret_cast<unsigned*>(&h1));
            hbase[(size_t)(ii + k) * 256 + t] = st;
            acc.x += v[k].x; acc.y += v[k].y; acc.z += v[k].z; acc.w += v[k].w;
        }
    }
    acc.x *= 0.015625f; acc.y *= 0.015625f;
    acc.z *= 0.015625f; acc.w *= 0.015625f;

    reinterpret_cast<float4*>(g_partials)[((size_t)b * SLICES0 + slice) * 256 + t] = acc;

    if (!arrive_last<SLICES0>(b)) return;
    last_block_epilogue<SLICES0, 1, 0>(b, bias, dout);
}

// Unpack helper: float4 of 8 halves -> 8 floats (e[0..7])
__device__ __forceinline__ void unpack8(const float4& hv, float* e)
{
    const __half2* hh = reinterpret_cast<const __half2*>(&hv);
    float2 a0 = __half22float2(hh[0]);
    float2 a1 = __half22float2(hh[1]);
    float2 a2 = __half22float2(hh[2]);
    float2 a3 = __half22float2(hh[3]);
    e[0] = a0.x; e[1] = a0.y; e[2] = a1.x; e[3] = a1.y;
    e[4] = a2.x; e[5] = a2.y; e[6] = a3.x; e[7] = a3.y;
}

// Load one fp16 row slice for this lane: 4 LDG.128
__device__ __forceinline__ void loadrow(float4* dst, const float4* rowp, int lane)
{
#pragma unroll
    for (int k = 0; k < 4; k++) dst[k] = rowp[lane + 32 * k];
}

// Process one row: dot -> softmax(64 j) -> weighted accumulate.
// hv: 4 packed float4 (32 halves). Unpacked twice (dot, then accumulate).
__device__ __forceinline__ void process_row(
    const float4* hv, const float4* wsh, int lane, float4* acc)
{
    float p[4];
#pragma unroll
    for (int k = 0; k < 4; k++) {
        int g = lane + 32 * k;
        float4 wa = wsh[2 * g], wb = wsh[2 * g + 1];
        float e[8];
        unpack8(hv[k], e);
        float t = e[0]*wa.x + e[1]*wa.y + e[2]*wa.z + e[3]*wa.w
                + e[4]*wb.x + e[5]*wb.y + e[6]*wb.z + e[7]*wb.w;
        t += __shfl_xor_sync(0xffffffffu, t, 1);   // full dot over d=16 (lane pair)
        p[k] = t;
    }
    float m = fmaxf(fmaxf(p[0], p[1]), fmaxf(p[2], p[3]));
    m = fmaxf(m, __shfl_xor_sync(0xffffffffu, m, 2));
    m = fmaxf(m, __shfl_xor_sync(0xffffffffu, m, 4));
    m = fmaxf(m, __shfl_xor_sync(0xffffffffu, m, 8));
    m = fmaxf(m, __shfl_xor_sync(0xffffffffu, m, 16));
    float a[4], s = 0.f;
#pragma unroll
    for (int k = 0; k < 4; k++) { a[k] = __expf(p[k] - m); s += a[k]; }
    s += __shfl_xor_sync(0xffffffffu, s, 2);
    s += __shfl_xor_sync(0xffffffffu, s, 4);
    s += __shfl_xor_sync(0xffffffffu, s, 8);
    s += __shfl_xor_sync(0xffffffffu, s, 16);
    float inv = 1.0f / s;
#pragma unroll
    for (int k = 0; k < 4; k++) {
        float ak = a[k] * inv;
        float e[8];
        unpack8(hv[k], e);   // re-unpack (cheap ALU; avoids 64-reg xv arrays)
        acc[2*k].x   = fmaf(ak, e[0], acc[2*k].x);
        acc[2*k].y   = fmaf(ak, e[1], acc[2*k].y);
        acc[2*k].z   = fmaf(ak, e[2], acc[2*k].z);
        acc[2*k].w   = fmaf(ak, e[3], acc[2*k].w);
        acc[2*k+1].x = fmaf(ak, e[4], acc[2*k+1].x);
        acc[2*k+1].y = fmaf(ak, e[5], acc[2*k+1].y);
        acc[2*k+1].z = fmaf(ak, e[6], acc[2*k+1].z);
        acc[2*k+1].w = fmaf(ak, e[7], acc[2*k+1].w);
    }
}

// ---------------------------------------------------------------------------
// Weighted passes over the fp16 shadow: row-per-warp, SOFTWARE-PIPELINED
// ping-pong (U/V): next row's 4 LDG.128 are always in flight while the
// current row computes -> sustained MLP without register blow-up.
// fp16 mapping: float4 g = lane + 32k (k=0..3) -> halves [8g, 8g+8)
//   -> capsule j = (lane>>1) + 16k. Dot: xor 1. Softmax: xor 2..16.
// ---------------------------------------------------------------------------
template<int OW_MODE, int FINAL_OUT, int REVERSE>
__global__ void __launch_bounds__(256, 2)
route_passH(const float* __restrict__ bias, float* __restrict__ dout)
{
    const int b     = blockIdx.x >> 3;
    const int slice = blockIdx.x & 7;
    const int wloc  = threadIdx.x >> 5;
    const int wb    = (slice << 3) | wloc;
    const int lane  = threadIdx.x & 31;

    __shared__ float4 wsh[256];            // 4 KB: ow vector for this b
    __shared__ float4 sbuf[WPBLK * 256];   // 32 KB: tail reduce

    {
        const float4* owp = reinterpret_cast<const float4*>(g_ow) + (size_t)b * 256;
        wsh[threadIdx.x] = owp[threadIdx.x];
    }
    __syncthreads();

    float4 acc[8];
#pragma unroll
    for (int k = 0; k < 8; k++) acc[k] = make_float4(0.f, 0.f, 0.f, 0.f);

    const float4* hbase = reinterpret_cast<const float4*>(g_xh)
        + ((size_t)b * NIN + (size_t)wb * IPW) * 128;   // 128 float4 per row

    // row index helper (zigzag traversal)
#define RIDX(r) (REVERSE ? (IPW - 1 - (r)) : (r))

    float4 U[4], V[4];
    loadrow(U, hbase + (size_t)RIDX(0) * 128, lane);

#pragma unroll 2
    for (int r = 0; r < IPW; r += 2) {
        loadrow(V, hbase + (size_t)RIDX(r + 1) * 128, lane);   // in flight during U
        process_row(U, wsh, lane, acc);
        if (r + 2 < IPW)
            loadrow(U, hbase + (size_t)RIDX(r + 2) * 128, lane); // in flight during V
        process_row(V, wsh, lane, acc);
    }
#undef RIDX

    // in-block reduce: write accs to canonical float4 positions
#pragma unroll
    for (int k = 0; k < 4; k++) {
        int g = lane + 32 * k;
        sbuf[wloc * 256 + 2 * g]     = acc[2 * k];
        sbuf[wloc * 256 + 2 * g + 1] = acc[2 * k + 1];
    }
    __syncthreads();

    const int t = threadIdx.x;
    float4 s = make_float4(0.f, 0.f, 0.f, 0.f);
#pragma unroll
    for (int w2 = 0; w2 < WPBLK; w2++) {
        float4 v = sbuf[w2 * 256 + t];
        s.x += v.x; s.y += v.y; s.z += v.z; s.w += v.w;
    }
    reinterpret_cast<float4*>(g_partials)[((size_t)b * SLICES + slice) * 256 + t] = s;

    if (!arrive_last<SLICES>(b)) return;
    last_block_epilogue<SLICES, OW_MODE, FINAL_OUT>(b, bias, dout);
}

extern "C" void kernel_launch(void* const* d_in, const int* in_sizes, int n_in,
                              void* d_out, int out_size)
{
    const float* x    = (const float*)d_in[0];   // [32, 2048, 64, 16]
    const float* bias = (const float*)d_in[1];   // [64, 16]
    float* out = (float*)d_out;                  // [32, 64, 16]

    (void)in_sizes; (void)n_in; (void)out_size;

    dim3 g0(NB * SLICES0), gW(NB * SLICES), blk(256);

    // Round 0 (forward, column-mapped): uniform 1/64 + fp16 shadow; g_ow = out0
    route_pass0<<<g0, blk>>>(x, bias, out);
    // Round 1 (REVERSE over shadow): softmax(dot(x, out0)); g_ow = out0+out1
    route_passH<2, 0, 1><<<gW, blk>>>(bias, out);
    // Round 2 (forward over shadow): softmax(dot(x, out0+out1)); write output
    route_passH<0, 1, 0><<<gW, blk>>>(bias, out);
}